// round 7
// baseline (speedup 1.0000x reference)
#include <cuda_runtime.h>
#include <cstdint>

// Problem constants
#define BB     64
#define SS     2048
#define INDIM  512
#define HH     512
#define CL     8            // cluster size (j-split of W_hh)
#define NCTA   128          // 16 clusters x 8 CTAs
#define GR     4            // batch groups per cluster (1 batch each)
#define BLK_ULL 264         // 528 floats: 512 + 4 pad per 128 (bank stagger)
#define BLK_BYTES 2112

typedef unsigned long long ull;

// ---------------- packed f32x2 helpers (FFMA2 path, sm_103a) ----------------
__device__ __forceinline__ void ffma2(ull& acc, ull a, ull b) {
    asm volatile("fma.rn.f32x2 %0, %1, %2, %0;" : "+l"(acc) : "l"(a), "l"(b));
}
__device__ __forceinline__ ull pack2(float x) {
    ull r; asm("mov.b64 %0, {%1, %1};" : "=l"(r) : "f"(x)); return r;
}
__device__ __forceinline__ float2 unpack2(ull v) {
    float2 r; asm("mov.b64 {%0, %1}, %2;" : "=f"(r.x), "=f"(r.y) : "l"(v)); return r;
}
__device__ __forceinline__ uint32_t smem_u32(const void* p) {
    uint32_t a;
    asm("{ .reg .u64 t; cvta.to.shared.u64 t, %1; cvt.u32.u64 %0, t; }" : "=r"(a) : "l"(p));
    return a;
}
__device__ __forceinline__ uint32_t mapa_rank(uint32_t laddr, uint32_t rank) {
    uint32_t r;
    asm("mapa.shared::cluster.u32 %0, %1, %2;" : "=r"(r) : "r"(laddr), "r"(rank));
    return r;
}
__device__ __forceinline__ void mbar_init(uint32_t mbar, uint32_t cnt) {
    asm volatile("mbarrier.init.shared.b64 [%0], %1;" :: "r"(mbar), "r"(cnt) : "memory");
}
__device__ __forceinline__ void mbar_arrive_expect_tx(uint32_t mbar, uint32_t tx) {
    asm volatile("mbarrier.arrive.expect_tx.shared.b64 _, [%0], %1;"
                 :: "r"(mbar), "r"(tx) : "memory");
}
__device__ __forceinline__ void mbar_wait_cluster(uint32_t mbar, uint32_t parity) {
    asm volatile(
        "{\n\t.reg .pred P;\n\t"
        "WL_%=:\n\t"
        "mbarrier.try_wait.parity.acquire.cluster.shared::cta.b64 P, [%0], %1, 0x989680;\n\t"
        "@!P bra WL_%=;\n\t}"
        :: "r"(mbar), "r"(parity) : "memory");
}
// remote smem store carrying complete_tx to the remote rank's mbarrier
__device__ __forceinline__ void st_async_b64(uint32_t raddr, ull v, uint32_t rmbar) {
    asm volatile("st.async.shared::cluster.mbarrier::complete_tx::bytes.b64 [%0], %1, [%2];"
                 :: "r"(raddr), "l"(v), "r"(rmbar) : "memory");
}

// ---------------- Phase 1: x_proj = inputs @ W_ih^T + b_ih ----------------
__global__ __launch_bounds__(256) void xproj_kernel(
    const float* __restrict__ A, const float* __restrict__ W,
    const float* __restrict__ bias, float* __restrict__ C) {
    __shared__ float As[16][132];
    __shared__ float Bs[16][132];

    const int tid = threadIdx.x;
    const int m0 = blockIdx.x * 128;
    const int n0 = blockIdx.y * 128;
    const int lr = tid >> 2;
    const int lk = (tid & 3) << 2;
    const int tx = tid & 15;
    const int ty = tid >> 4;

    ull acc[8][4];
#pragma unroll
    for (int i = 0; i < 8; i++)
#pragma unroll
        for (int j = 0; j < 4; j++) acc[i][j] = 0ull;

    for (int k0 = 0; k0 < INDIM; k0 += 16) {
        float4 a0 = *(const float4*)(A + (size_t)(m0 + lr) * INDIM + k0 + lk);
        float4 a1 = *(const float4*)(A + (size_t)(m0 + lr + 64) * INDIM + k0 + lk);
        float4 w0 = *(const float4*)(W + (size_t)(n0 + lr) * INDIM + k0 + lk);
        float4 w1 = *(const float4*)(W + (size_t)(n0 + lr + 64) * INDIM + k0 + lk);
        __syncthreads();
        As[lk + 0][lr] = a0.x; As[lk + 1][lr] = a0.y; As[lk + 2][lr] = a0.z; As[lk + 3][lr] = a0.w;
        As[lk + 0][lr + 64] = a1.x; As[lk + 1][lr + 64] = a1.y; As[lk + 2][lr + 64] = a1.z; As[lk + 3][lr + 64] = a1.w;
        Bs[lk + 0][lr] = w0.x; Bs[lk + 1][lr] = w0.y; Bs[lk + 2][lr] = w0.z; Bs[lk + 3][lr] = w0.w;
        Bs[lk + 0][lr + 64] = w1.x; Bs[lk + 1][lr + 64] = w1.y; Bs[lk + 2][lr + 64] = w1.z; Bs[lk + 3][lr + 64] = w1.w;
        __syncthreads();
#pragma unroll
        for (int k = 0; k < 16; k++) {
            float4 am0 = *(const float4*)&As[k][ty * 4];
            float4 am1 = *(const float4*)&As[k][64 + ty * 4];
            ulonglong2 bn0 = *(const ulonglong2*)&Bs[k][tx * 4];
            ulonglong2 bn1 = *(const ulonglong2*)&Bs[k][64 + tx * 4];
            float am[8] = {am0.x, am0.y, am0.z, am0.w, am1.x, am1.y, am1.z, am1.w};
#pragma unroll
            for (int i = 0; i < 8; i++) {
                ull ap = pack2(am[i]);
                ffma2(acc[i][0], ap, bn0.x);
                ffma2(acc[i][1], ap, bn0.y);
                ffma2(acc[i][2], ap, bn1.x);
                ffma2(acc[i][3], ap, bn1.y);
            }
        }
    }

    float4 bA = *(const float4*)(bias + n0 + tx * 4);
    float4 bBv = *(const float4*)(bias + n0 + 64 + tx * 4);
#pragma unroll
    for (int i = 0; i < 8; i++) {
        int m = m0 + ((i < 4) ? (ty * 4 + i) : (64 + ty * 4 + (i - 4)));
        float2 c0 = unpack2(acc[i][0]);
        float2 c1 = unpack2(acc[i][1]);
        float2 c2 = unpack2(acc[i][2]);
        float2 c3 = unpack2(acc[i][3]);
        float4 o0 = make_float4(c0.x + bA.x, c0.y + bA.y, c1.x + bA.z, c1.y + bA.w);
        float4 o1 = make_float4(c2.x + bBv.x, c2.y + bBv.y, c3.x + bBv.z, c3.y + bBv.w);
        *(float4*)(C + (size_t)m * HH + n0 + tx * 4) = o0;
        *(float4*)(C + (size_t)m * HH + n0 + 64 + tx * 4) = o1;
    }
}

// ---------------- Phase 2: 4-way interleaved warp-autonomous scan ----------
// Cluster of 8 CTAs = 4 batches, each its own pipeline group. Rank r owns
// j in [64r, 64r+64). Warp w owns j-sub-block [8w, 8w+8); lane = (j, kq).
// No __syncthreads in the loop. Scatter = ONE st.async.b64 per warp per
// GSTEP: lane i sends j-pair (i&3) of this warp to rank (i>>2).
__global__ __launch_bounds__(256, 1) __cluster_dims__(CL, 1, 1)
void rnn_scan_kernel(
    const float* __restrict__ h0, const float* __restrict__ W_hh,
    const float* __restrict__ b_hh, float* __restrict__ out, int write_hfinal) {
    __shared__ __align__(16) ull hsp[GR][2][BLK_ULL];  // [grp][slot][padded h]
    __shared__ ull mbars[GR][2];

    const int tid = threadIdx.x;
    const int w = tid >> 5;            // warp -> j-sub-block
    const int l = tid & 31;
    uint32_t rank;
    asm("mov.u32 %0, %%cluster_ctarank;" : "=r"(rank));
    const int j0 = (int)rank * 64;
    const int b0 = (blockIdx.x >> 3) * 4;
    const int jl = l & 7;              // j within warp's 8
    const int q = l >> 3;              // k-quarter (128 k)
    const int gjl = j0 + 8 * w + jl;   // global j

    // ---- W row quarter into registers: 64 k-pairs for (row gjl, quarter q) --
    ull Wr[64];
    {
        const ull* wrow = (const ull*)(W_hh + (size_t)gjl * HH) + q * 64;
#pragma unroll
        for (int p = 0; p < 64; p++) Wr[p] = wrow[p];
    }
    const float bh = b_hh[gjl];

    // ---- init h slot 0 of all groups from h0 (staggered layout) ----
#pragma unroll
    for (int g = 0; g < GR; g++) {
        float* hf = (float*)&hsp[g][0][0];
        for (int k = tid; k < HH; k += 256)
            hf[k + (k >> 7) * 4] = h0[(size_t)(b0 + g) * HH + k];
    }

    const uint32_t mb_local = smem_u32(&mbars[0][0]);
    if (tid == 0) {
#pragma unroll
        for (int i = 0; i < 2 * GR; i++) {
            mbar_init(mb_local + 8 * i, 1);
            mbar_arrive_expect_tx(mb_local + 8 * i, 2048u);
        }
        asm volatile("fence.mbarrier_init.release.cluster;" ::: "memory");
    }
    __syncthreads();
    asm volatile("barrier.cluster.arrive.aligned;" ::: "memory");
    asm volatile("barrier.cluster.wait.aligned;" ::: "memory");

    // per-lane remote scatter addresses: lane i -> rank (i>>2), j-pair (i&3)
    const uint32_t hbase = smem_u32(&hsp[0][0][0]);
    const int Kp = 32 * (int)rank + 4 * w + (l & 3);         // dest k-pair idx
    const uint32_t lane_off = (uint32_t)(8 * Kp + (Kp >> 6) * 16);
    const uint32_t rdst = mapa_rank(hbase, (uint32_t)(l >> 2)) + lane_off;
    const uint32_t rmb  = mapa_rank(mb_local, (uint32_t)(l >> 2));

    // consumer view: this lane reads k-quarter q
    const ull* hq = &hsp[0][0][0] + q * 66;

    size_t ob[GR];
    float xp[GR], hl[GR];
#pragma unroll
    for (int g = 0; g < GR; g++) {
        ob[g] = (size_t)(b0 + g) * SS * HH + gjl;
        hl[g] = 0.f;
        xp[g] = (l < 8) ? __ldcs(out + ob[g]) : 0.f;
    }

#define GSTEP(T, S, G, PH)                                                      \
  {                                                                             \
    if ((T) > 0) {                                                              \
      mbar_wait_cluster(mb_local + ((G) * 2 + (S)) * 8, (PH));                  \
      if (tid == 0)                                                             \
        mbar_arrive_expect_tx(mb_local + ((G) * 2 + (S)) * 8, 2048u);           \
    }                                                                           \
    const ull* hb = hq + ((G) * 2 + (S)) * BLK_ULL;                             \
    ull a0 = 0, a1 = 0;                                                         \
    _Pragma("unroll")                                                           \
    for (int p = 0; p < 32; p++) {                                              \
      ulonglong2 hx = *(const ulonglong2*)(hb + 2 * p);                         \
      ffma2(a0, hx.x, Wr[2 * p]);                                               \
      ffma2(a1, hx.y, Wr[2 * p + 1]);                                           \
    }                                                                           \
    float2 f0 = unpack2(a0), f1 = unpack2(a1);                                  \
    float s = (f0.x + f0.y) + (f1.x + f1.y);                                    \
    s += __shfl_xor_sync(0xffffffffu, s, 8);                                    \
    s += __shfl_xor_sync(0xffffffffu, s, 16);                                   \
    float pre = xp[G] + s + bh;                                                 \
    float e = __expf(pre + pre);                                                \
    float hv = 1.f - __fdividef(2.f, e + 1.f);                                  \
    float v0 = __shfl_sync(0xffffffffu, hv, 2 * (l & 3));                       \
    float v1 = __shfl_sync(0xffffffffu, hv, 2 * (l & 3) + 1);                   \
    if ((T) + 1 < SS) {                                                         \
      ull v; asm("mov.b64 %0, {%1, %2};" : "=l"(v) : "f"(v0), "f"(v1));         \
      st_async_b64(rdst + (uint32_t)(((G) * 2 + ((S) ^ 1)) * BLK_BYTES), v,     \
                   rmb + (uint32_t)(((G) * 2 + ((S) ^ 1)) * 8));                \
    }                                                                           \
    if (l < 8) {                                                                \
      __stcs(out + ob[G] + (size_t)(T) * HH, hv);                               \
      hl[G] = hv;                                                               \
      if ((T) + 1 < SS) xp[G] = __ldcs(out + ob[G] + (size_t)((T) + 1) * HH);   \
    }                                                                           \
  }

    for (int t = 0; t < SS; t += 2) {
        const uint32_t p0 = ((t >> 1) + 1) & 1;   // slot0 waits at t (t>=2)
        const uint32_t p1 = (t >> 1) & 1;         // slot1 waits at t+1
        GSTEP(t, 0, 0, p0);
        GSTEP(t, 0, 1, p0);
        GSTEP(t, 0, 2, p0);
        GSTEP(t, 0, 3, p0);
        GSTEP(t + 1, 1, 0, p1);
        GSTEP(t + 1, 1, 1, p1);
        GSTEP(t + 1, 1, 2, p1);
        GSTEP(t + 1, 1, 3, p1);
    }
#undef GSTEP

    if (write_hfinal && l < 8) {
#pragma unroll
        for (int g = 0; g < GR; g++)
            out[(size_t)BB * SS * HH + (size_t)(b0 + g) * HH + gjl] = hl[g];
    }
}

// ---------------- launch ----------------
extern "C" void kernel_launch(void* const* d_in, const int* in_sizes, int n_in,
                              void* d_out, int out_size) {
    const float* inputs = (const float*)d_in[0];   // [64, 2048, 512]
    const float* h0     = (const float*)d_in[1];   // [64, 512]
    const float* W_ih   = (const float*)d_in[2];   // [512, 512]
    const float* W_hh   = (const float*)d_in[3];   // [512, 512]
    const float* b_ih   = (const float*)d_in[4];   // [512]
    const float* b_hh   = (const float*)d_in[5];   // [512]
    float* out = (float*)d_out;

    // Phase 1: x_proj into the outs region of d_out (scan overwrites in place)
    dim3 g1((BB * SS) / 128, HH / 128, 1);
    xproj_kernel<<<g1, 256>>>(inputs, W_ih, b_ih, out);

    // Phase 2: 16 clusters of 8 CTAs; 4 interleaved single-batch pipelines
    long long need = (long long)BB * SS * HH + (long long)BB * HH;
    int wf = ((long long)out_size >= need) ? 1 : 0;
    rnn_scan_kernel<<<NCTA, 256>>>(h0, W_hh, b_hh, out, wf);
}

// round 8
// speedup vs baseline: 1.0458x; 1.0458x over previous
#include <cuda_runtime.h>
#include <cstdint>

// Problem constants
#define BB     64
#define SS     2048
#define INDIM  512
#define HH     512
#define NCTA   128
#define NCL    16          // logical clusters of 8 CTAs (coordinated via L2)
#define QFULL  32u         // 8 ranks x 4 producing warps per phase

typedef unsigned long long ull;

// ---------------- packed f32x2 helpers (FFMA2 path, sm_103a) ----------------
__device__ __forceinline__ void ffma2(ull& acc, ull a, ull b) {
    asm volatile("fma.rn.f32x2 %0, %1, %2, %0;" : "+l"(acc) : "l"(a), "l"(b));
}
__device__ __forceinline__ ull pack2(float x) {
    ull r; asm("mov.b64 %0, {%1, %1};" : "=l"(r) : "f"(x)); return r;
}
__device__ __forceinline__ ull packf2(float x, float y) {
    ull r; asm("mov.b64 %0, {%1, %2};" : "=l"(r) : "f"(x), "f"(y)); return r;
}
__device__ __forceinline__ float2 unpack2(ull v) {
    float2 r; asm("mov.b64 {%0, %1}, %2;" : "=f"(r.x), "=f"(r.y) : "l"(v)); return r;
}
__device__ __forceinline__ unsigned ld_acq(const unsigned* p) {
    unsigned v;
    asm volatile("ld.acquire.gpu.u32 %0, [%1];" : "=r"(v) : "l"(p) : "memory");
    return v;
}
__device__ __forceinline__ void red_rel(unsigned* p, unsigned v) {
    asm volatile("red.release.gpu.add.u32 [%0], %1;" :: "l"(p), "r"(v) : "memory");
}

// ---------------- L2 exchange state (zeroed per launch by zero_cnt_kernel) --
__device__ __align__(16) float g_hx[NCL][2][2][2][HH]; // [cl][grp][slot][b][j]
__device__ unsigned g_cnt[NCL][2][2];                  // [cl][grp][slot]

__global__ void zero_cnt_kernel() {
    int i = threadIdx.x;
    if (i < NCL * 2 * 2) ((unsigned*)g_cnt)[i] = 0u;
}

// ---------------- Phase 1: x_proj = inputs @ W_ih^T + b_ih ----------------
__global__ __launch_bounds__(256) void xproj_kernel(
    const float* __restrict__ A, const float* __restrict__ W,
    const float* __restrict__ bias, float* __restrict__ C) {
    __shared__ float As[16][132];
    __shared__ float Bs[16][132];

    const int tid = threadIdx.x;
    const int m0 = blockIdx.x * 128;
    const int n0 = blockIdx.y * 128;
    const int lr = tid >> 2;
    const int lk = (tid & 3) << 2;
    const int tx = tid & 15;
    const int ty = tid >> 4;

    ull acc[8][4];
#pragma unroll
    for (int i = 0; i < 8; i++)
#pragma unroll
        for (int j = 0; j < 4; j++) acc[i][j] = 0ull;

    for (int k0 = 0; k0 < INDIM; k0 += 16) {
        float4 a0 = *(const float4*)(A + (size_t)(m0 + lr) * INDIM + k0 + lk);
        float4 a1 = *(const float4*)(A + (size_t)(m0 + lr + 64) * INDIM + k0 + lk);
        float4 w0 = *(const float4*)(W + (size_t)(n0 + lr) * INDIM + k0 + lk);
        float4 w1 = *(const float4*)(W + (size_t)(n0 + lr + 64) * INDIM + k0 + lk);
        __syncthreads();
        As[lk + 0][lr] = a0.x; As[lk + 1][lr] = a0.y; As[lk + 2][lr] = a0.z; As[lk + 3][lr] = a0.w;
        As[lk + 0][lr + 64] = a1.x; As[lk + 1][lr + 64] = a1.y; As[lk + 2][lr + 64] = a1.z; As[lk + 3][lr + 64] = a1.w;
        Bs[lk + 0][lr] = w0.x; Bs[lk + 1][lr] = w0.y; Bs[lk + 2][lr] = w0.z; Bs[lk + 3][lr] = w0.w;
        Bs[lk + 0][lr + 64] = w1.x; Bs[lk + 1][lr + 64] = w1.y; Bs[lk + 2][lr + 64] = w1.z; Bs[lk + 3][lr + 64] = w1.w;
        __syncthreads();
#pragma unroll
        for (int k = 0; k < 16; k++) {
            float4 am0 = *(const float4*)&As[k][ty * 4];
            float4 am1 = *(const float4*)&As[k][64 + ty * 4];
            ulonglong2 bn0 = *(const ulonglong2*)&Bs[k][tx * 4];
            ulonglong2 bn1 = *(const ulonglong2*)&Bs[k][64 + tx * 4];
            float am[8] = {am0.x, am0.y, am0.z, am0.w, am1.x, am1.y, am1.z, am1.w};
#pragma unroll
            for (int i = 0; i < 8; i++) {
                ull ap = pack2(am[i]);
                ffma2(acc[i][0], ap, bn0.x);
                ffma2(acc[i][1], ap, bn0.y);
                ffma2(acc[i][2], ap, bn1.x);
                ffma2(acc[i][3], ap, bn1.y);
            }
        }
    }

    float4 bA = *(const float4*)(bias + n0 + tx * 4);
    float4 bBv = *(const float4*)(bias + n0 + 64 + tx * 4);
#pragma unroll
    for (int i = 0; i < 8; i++) {
        int m = m0 + ((i < 4) ? (ty * 4 + i) : (64 + ty * 4 + (i - 4)));
        float2 c0 = unpack2(acc[i][0]);
        float2 c1 = unpack2(acc[i][1]);
        float2 c2 = unpack2(acc[i][2]);
        float2 c3 = unpack2(acc[i][3]);
        float4 o0 = make_float4(c0.x + bA.x, c0.y + bA.y, c1.x + bA.z, c1.y + bA.w);
        float4 o1 = make_float4(c2.x + bBv.x, c2.y + bBv.y, c3.x + bBv.z, c3.y + bBv.w);
        *(float4*)(C + (size_t)m * HH + n0 + tx * 4) = o0;
        *(float4*)(C + (size_t)m * HH + n0 + 64 + tx * 4) = o1;
    }
}

// ---------------- Phase 2: scan with L2 message-passing exchange ----------
// 16 logical clusters of 8 CTAs (no HW cluster). Rank r owns j-slice
// [64r,64r+64); W in registers. Producers STG.cg their 64x2 h values once to
// g_hx and release-increment the (grp,slot) counter; consumers acquire-poll
// the counter, stage 2KB L2->smem, and compute. 2 groups x 2 batches.
__global__ __launch_bounds__(256, 1) void rnn_scan_kernel(
    const float* __restrict__ h0, const float* __restrict__ W_hh,
    const float* __restrict__ b_hh, float* __restrict__ out, int write_hfinal) {
    __shared__ __align__(16) ull hsp[2][2][256][2];   // [grp][slot][kp][b] 16KB
    __shared__ float red[2][2][8][32][2];             // [grp][jpar][w][jp][b] 8KB

    const int tid = threadIdx.x;
    const int w = tid >> 5;           // warp -> k-chunk [64w, 64w+64)
    const int l = tid & 31;           // lane -> j-pair {2l, 2l+1}
    const int rank = blockIdx.x & 7;
    const int ci = blockIdx.x >> 3;
    const int j0 = rank * 64;
    const int b0 = ci * 4;
    const int obl = (tid >> 6) & 1;   // batch within group
    const int oj = tid & 63;          // j within slice
    const int gj = j0 + oj;

    // ---- W slice into registers, k-paired ----
    ull Wp0[32], Wp1[32];
    {
        const ull* w0p = (const ull*)(W_hh + (size_t)(j0 + 2 * l) * HH + w * 64);
        const ull* w1p = (const ull*)(W_hh + (size_t)(j0 + 2 * l + 1) * HH + w * 64);
#pragma unroll
        for (int p = 0; p < 32; p++) { Wp0[p] = w0p[p]; Wp1[p] = w1p[p]; }
    }
    const float bh = b_hh[gj];

    // ---- init: publish own h0 slices for both groups, slot 0 ----
    if (tid < 128) {
        __stcg(&g_hx[ci][0][0][obl][gj], h0[(size_t)(b0 + obl) * HH + gj]);
        __stcg(&g_hx[ci][1][0][obl][gj], h0[(size_t)(b0 + 2 + obl) * HH + gj]);
    }
    __syncwarp();
    if (w < 4 && l == 0) {
        red_rel(&g_cnt[ci][0][0], 1u);
        red_rel(&g_cnt[ci][1][0], 1u);
    }

    const int skq = tid & 127;        // stage: k-quad index
    const int sb = tid >> 7;          // stage: batch index

    unsigned e00 = QFULL, e01 = QFULL, e10 = QFULL, e11 = QFULL; // exp[G][S]

    const size_t obA = (size_t)(b0 + obl) * SS * HH + gj;
    const size_t obB = (size_t)(b0 + 2 + obl) * SS * HH + gj;
    float xpA = 0.f, xpB = 0.f, hlA = 0.f, hlB = 0.f;
    if (tid < 128) { xpA = __ldcs(out + obA); xpB = __ldcs(out + obB); }

#define GSTEP(T, S, G, EXP, XP, HL, OB)                                         \
  {                                                                             \
    { const unsigned* cp = &g_cnt[ci][G][S];                                    \
      while ((int)(ld_acq(cp) - (EXP)) < 0) { }                                 \
      (EXP) += QFULL; }                                                         \
    { float4 v = __ldcg((const float4*)&g_hx[ci][G][S][sb][skq * 4]);           \
      hsp[G][S][2 * skq][sb] = packf2(v.x, v.y);                                \
      hsp[G][S][2 * skq + 1][sb] = packf2(v.z, v.w); }                          \
    __syncthreads();                                                            \
    const ull* hb = &hsp[G][S][w * 32][0];                                      \
    ull a00 = 0, a01 = 0, a10 = 0, a11 = 0;                                     \
    _Pragma("unroll")                                                           \
    for (int p = 0; p < 32; p++) {                                              \
      ulonglong2 hx = *(const ulonglong2*)(hb + p * 2);                         \
      ull w0 = Wp0[p], w1 = Wp1[p];                                             \
      ffma2(a00, hx.x, w0); ffma2(a01, hx.y, w0);                               \
      ffma2(a10, hx.x, w1); ffma2(a11, hx.y, w1);                               \
    }                                                                           \
    { float2 f; float2 ra, rb;                                                  \
      f = unpack2(a00); ra.x = f.x + f.y; f = unpack2(a01); ra.y = f.x + f.y;   \
      f = unpack2(a10); rb.x = f.x + f.y; f = unpack2(a11); rb.y = f.x + f.y;   \
      *(float2*)&red[G][0][w][l][0] = ra;                                       \
      *(float2*)&red[G][1][w][l][0] = rb; }                                     \
    __syncthreads();                                                            \
    if (tid < 128) {                                                            \
      const float* rf = &red[G][oj & 1][0][oj >> 1][obl];                       \
      float sum = rf[0] + rf[64] + rf[128] + rf[192]                            \
                + rf[256] + rf[320] + rf[384] + rf[448];                        \
      float pre = XP + sum + bh;                                                \
      float e = __expf(pre + pre);                                              \
      float hv = 1.f - __fdividef(2.f, e + 1.f);                                \
      if ((T) + 1 < SS) __stcg(&g_hx[ci][G][(S) ^ 1][obl][gj], hv);             \
      __syncwarp();                                                             \
      if (((T) + 1 < SS) && l == 0) red_rel(&g_cnt[ci][G][(S) ^ 1], 1u);        \
      __stcs(out + OB + (size_t)(T) * HH, hv);                                  \
      HL = hv;                                                                  \
      if ((T) + 1 < SS) XP = __ldcs(out + OB + (size_t)((T) + 1) * HH);         \
    }                                                                           \
  }

    for (int t = 0; t < SS; t += 2) {
        GSTEP(t,     0, 0, e00, xpA, hlA, obA);
        GSTEP(t,     0, 1, e10, xpB, hlB, obB);
        GSTEP(t + 1, 1, 0, e01, xpA, hlA, obA);
        GSTEP(t + 1, 1, 1, e11, xpB, hlB, obB);
    }
#undef GSTEP

    if (write_hfinal && tid < 128) {
        out[(size_t)BB * SS * HH + (size_t)(b0 + obl) * HH + gj] = hlA;
        out[(size_t)BB * SS * HH + (size_t)(b0 + 2 + obl) * HH + gj] = hlB;
    }
}

// ---------------- launch ----------------
extern "C" void kernel_launch(void* const* d_in, const int* in_sizes, int n_in,
                              void* d_out, int out_size) {
    const float* inputs = (const float*)d_in[0];   // [64, 2048, 512]
    const float* h0     = (const float*)d_in[1];   // [64, 512]
    const float* W_ih   = (const float*)d_in[2];   // [512, 512]
    const float* W_hh   = (const float*)d_in[3];   // [512, 512]
    const float* b_ih   = (const float*)d_in[4];   // [512]
    const float* b_hh   = (const float*)d_in[5];   // [512]
    float* out = (float*)d_out;

    // Reset L2 exchange counters (replay-safe), then x_proj, then scan.
    zero_cnt_kernel<<<1, 64>>>();
    dim3 g1((BB * SS) / 128, HH / 128, 1);
    xproj_kernel<<<g1, 256>>>(inputs, W_ih, b_ih, out);

    long long need = (long long)BB * SS * HH + (long long)BB * HH;
    int wf = ((long long)out_size >= need) ? 1 : 0;
    rnn_scan_kernel<<<NCTA, 256>>>(h0, W_hh, b_hh, out, wf);
}